// round 12
// baseline (speedup 1.0000x reference)
#include <cuda_runtime.h>
#include <math.h>
#include <stdint.h>

// ---------------- problem constants ----------------
#define D_MODEL 2048
#define D_STATE 16
#define D_CONV  4
#define D_INNER 4096
#define DT_RANK 128
#define B_SZ    2
#define SEQ     1024
#define NTOK    (B_SZ * SEQ)             // 2048 tokens (= GEMM M)
#define NPROJ   (DT_RANK + 2 * D_STATE)  // 160

// ---------------- static device scratch (fp32) ----------------
__device__ float g_x [NTOK * D_INNER];      // in_proj x half (pre-conv)
__device__ float g_zs[NTOK * D_INNER];      // silu(z)
__device__ float g_xc[NTOK * D_INNER];      // conv+silu
__device__ float g_Ppart[4 * NTOK * NPROJ]; // split-K partials
__device__ float g_Pf[NTOK * DT_RANK];      // dt_low fp32
__device__ float g_BC[NTOK * 2 * D_STATE];  // [tok][B(16)|C(16)]
__device__ float g_dt[NTOK * D_INNER];
__device__ float g_yf[NTOK * D_INNER];      // scan output (gated) fp32
__device__ float g_wcatf[NPROJ * D_INNER];  // packed x-proj weights fp32

// ---------------- int8 2-limb quantized operands ----------------
__device__ int8_t g_uq1  [NTOK * D_MODEL];        __device__ int8_t g_uq2  [NTOK * D_MODEL];
__device__ float  g_ufs  [NTOK];
__device__ int8_t g_winq1[2 * D_INNER * D_MODEL]; __device__ int8_t g_winq2[2 * D_INNER * D_MODEL];
__device__ float  g_winfs[2 * D_INNER];
__device__ int8_t g_woutq1[D_MODEL * D_INNER];    __device__ int8_t g_woutq2[D_MODEL * D_INNER];
__device__ float  g_woutfs[D_MODEL];
__device__ int8_t g_wdtq1[D_INNER * DT_RANK];     __device__ int8_t g_wdtq2[D_INNER * DT_RANK];
__device__ float  g_wdtfs[D_INNER];
__device__ int8_t g_wcatq1[NPROJ * D_INNER];      __device__ int8_t g_wcatq2[NPROJ * D_INNER];
__device__ float  g_wcatfs[NPROJ];
__device__ int8_t g_xcq1[NTOK * D_INNER];         __device__ int8_t g_xcq2[NTOK * D_INNER];
__device__ float  g_xcfs[NTOK];
__device__ int8_t g_Pq1 [NTOK * DT_RANK];         __device__ int8_t g_Pq2 [NTOK * DT_RANK];
__device__ float  g_Pfs [NTOK];
__device__ int8_t g_yq1 [NTOK * D_INNER];         __device__ int8_t g_yq2 [NTOK * D_INNER];
__device__ float  g_yfs [NTOK];

// ---------------- helpers ----------------
__device__ __forceinline__ uint32_t smem_u32(const void* p) {
    uint32_t a;
    asm("{ .reg .u64 t; cvta.to.shared.u64 t, %1; cvt.u32.u64 %0, t; }" : "=r"(a) : "l"(p));
    return a;
}
__device__ __forceinline__ float silu_f(float v) { return v * (1.0f / (1.0f + __expf(-v))); }
__device__ __forceinline__ float softplus_f(float v) {
    return fmaxf(v, 0.0f) + log1pf(__expf(-fabsf(v)));
}
__device__ __forceinline__ void cpa16(uint32_t dst, const void* src, int srcsz) {
    asm volatile("cp.async.cg.shared.global [%0], [%1], 16, %2;"
                 :: "r"(dst), "l"(src), "r"(srcsz) : "memory");
}
__device__ __forceinline__ void cp_commit() {
    asm volatile("cp.async.commit_group;" ::: "memory");
}
__device__ __forceinline__ void mma_s8(int* d, const uint32_t* a, uint32_t b0, uint32_t b1) {
    asm volatile(
        "mma.sync.aligned.m16n8k32.row.col.s32.s8.s8.s32 "
        "{%0,%1,%2,%3}, {%4,%5,%6,%7}, {%8,%9}, {%0,%1,%2,%3};"
        : "+r"(d[0]), "+r"(d[1]), "+r"(d[2]), "+r"(d[3])
        : "r"(a[0]), "r"(a[1]), "r"(a[2]), "r"(a[3]), "r"(b0), "r"(b1));
}
#define LDSM_X4(r0, r1, r2, r3, addr) \
    asm volatile("ldmatrix.sync.aligned.m8n8.x4.shared.b16 {%0,%1,%2,%3}, [%4];" \
                 : "=r"(r0), "=r"(r1), "=r"(r2), "=r"(r3) : "r"(addr))

// ---------------- per-row 2-limb int8 quantization ----------------
// v ~= fs * (128*q1 + q2), fs = rowmax/16256, |q1|<=127, |q2|<=64.
__global__ void quant_rows(const float* __restrict__ src,
                           int8_t* __restrict__ q1, int8_t* __restrict__ q2,
                           float* __restrict__ fs, int K) {
    const int r = blockIdx.x;
    const float* row = src + (size_t)r * K;
    const int tid = threadIdx.x;

    float m = 0.0f;
    for (int i = tid; i < K; i += 256) m = fmaxf(m, fabsf(row[i]));
    #pragma unroll
    for (int o = 16; o; o >>= 1) m = fmaxf(m, __shfl_xor_sync(0xffffffffu, m, o));
    __shared__ float wmax[8];
    if ((tid & 31) == 0) wmax[tid >> 5] = m;
    __syncthreads();
    if (tid == 0) {
        float s = wmax[0];
        #pragma unroll
        for (int w = 1; w < 8; w++) s = fmaxf(s, wmax[w]);
        s = fmaxf(s, 1e-20f);
        wmax[0] = s;
        fs[r] = s * (1.0f / 16256.0f);
    }
    __syncthreads();
    const float inv = 16256.0f / wmax[0];

    for (int i = tid * 4; i < K; i += 1024) {
        float4 v = *(const float4*)(row + i);
        float w0 = v.x * inv, w1 = v.y * inv, w2 = v.z * inv, w3 = v.w * inv;
        float a0 = rintf(w0 * 0.0078125f), a1 = rintf(w1 * 0.0078125f);
        float a2 = rintf(w2 * 0.0078125f), a3 = rintf(w3 * 0.0078125f);
        char c1[4] = { (char)(int)a0, (char)(int)a1, (char)(int)a2, (char)(int)a3 };
        char c2[4] = { (char)(int)rintf(w0 - 128.0f * a0), (char)(int)rintf(w1 - 128.0f * a1),
                       (char)(int)rintf(w2 - 128.0f * a2), (char)(int)rintf(w3 - 128.0f * a3) };
        *(char4*)(q1 + (size_t)r * K + i) = *(char4*)c1;
        *(char4*)(q2 + (size_t)r * K + i) = *(char4*)c2;
    }
}

__global__ void pack_wcat_kernel(const float* __restrict__ w_xdt,
                                 const float* __restrict__ w_xb,
                                 const float* __restrict__ w_xc) {
    int i = blockIdx.x * 256 + threadIdx.x;
    if (i >= NPROJ * D_INNER) return;
    int r = i / D_INNER, k = i - r * D_INNER;
    float v;
    if (r < DT_RANK)                v = w_xdt[r * D_INNER + k];
    else if (r < DT_RANK + D_STATE) v = w_xb[(r - DT_RANK) * D_INNER + k];
    else                            v = w_xc[(r - DT_RANK - D_STATE) * D_INNER + k];
    g_wcatf[i] = v;
}

// ---------------- int8 2-limb IMMA GEMM (mma.sync m16n8k32, sm_80 ISA) ----------------
// C = fsA[r]*fsB[c]*(16384*sum(q1a*q1b) + 128*sum(q1a*q2b + q2a*q1b))  [q2q2 dropped]
// 128x128x64 CTA tile, 512 threads, 4x4 warps (32x32 warp tiles),
// 3-stage cp.async pipeline, 80B-padded rows (conflict-free LDSM).
// mode: 1 in_proj   0 x-proj split-K partial   2 dt(softplus)   3 out
#define GBM 128
#define GBN 128
#define GBK 64
#define ROWB 80
#define TILE_B (128 * ROWB)          // 10240
#define SQ1A 0
#define SQ2A (TILE_B)
#define SQ1B (2 * TILE_B)
#define SQ2B (3 * TILE_B)
#define STAGE_B (4 * TILE_B)         // 40960
#define NSTAGE 3
#define GSMEM (NSTAGE * STAGE_B)     // 122880

__global__ void __launch_bounds__(512, 1) gemm_s8(
    int N, int K, int ksl,
    const int8_t* __restrict__ Aq1, const int8_t* __restrict__ Aq2,
    const int8_t* __restrict__ Bq1, const int8_t* __restrict__ Bq2,
    const float* __restrict__ fsA, const float* __restrict__ fsB,
    const float* __restrict__ bias, float* __restrict__ outp, int mode)
{
    extern __shared__ char sm[];
    const uint32_t smb = smem_u32(sm);
    const int tid  = threadIdx.x;
    const int lane = tid & 31;
    const int wid  = tid >> 5;           // 0..15
    const int wm   = wid >> 2;           // 0..3
    const int wn   = wid & 3;            // 0..3

    const int brow  = blockIdx.y * GBM;
    const int bcol  = blockIdx.x * GBN;
    const int kbase = blockIdx.z * ksl;
    const int nchunks = ksl / GBK;

    int accM[2][4][4], accC[2][4][4];
    #pragma unroll
    for (int i = 0; i < 2; i++)
        #pragma unroll
        for (int j = 0; j < 4; j++)
            #pragma unroll
            for (int q = 0; q < 4; q++) { accM[i][j][q] = 0; accC[i][j][q] = 0; }

    // loader: 512 threads cover one 128x64B tile per cpa16 (r = tid>>2, c16 = tid&3)
    const int lr = tid >> 2;
    const int lc = tid & 3;
    auto load_stage = [&](int stage, int k0) {
        uint32_t sb = smb + stage * STAGE_B;
        uint32_t soff = (uint32_t)(lr * ROWB + lc * 16);
        size_t ga = (size_t)(brow + lr) * K + k0 + lc * 16;
        cpa16(sb + SQ1A + soff, Aq1 + ga, 16);
        cpa16(sb + SQ2A + soff, Aq2 + ga, 16);
        int gr = bcol + lr;
        int sz = (gr < N) ? 16 : 0;
        int grc = (gr < N) ? gr : 0;
        size_t gb = (size_t)grc * K + k0 + lc * 16;
        cpa16(sb + SQ1B + soff, Bq1 + gb, sz);
        cpa16(sb + SQ2B + soff, Bq2 + gb, sz);
        cp_commit();
    };

    load_stage(0, kbase);
    if (nchunks > 1) load_stage(1, kbase + GBK);
    else cp_commit();

    // ldmatrix lane offsets (same byte-layout as validated bf16 path)
    const uint32_t aOff = (uint32_t)((wm * 32 + (lane & 15)) * ROWB + (lane >> 4) * 16);
    const uint32_t bOff = (uint32_t)((wn * 32 + ((lane >> 4) & 1) * 8 + (lane & 7)) * ROWB
                                     + ((lane >> 3) & 1) * 16);

    for (int c = 0; c < nchunks; c++) {
        asm volatile("cp.async.wait_group 1;" ::: "memory");
        __syncthreads();
        if (c + 2 < nchunks) load_stage((c + 2) % NSTAGE, kbase + (c + 2) * GBK);
        else cp_commit();

        const uint32_t sb = smb + (c % NSTAGE) * STAGE_B;
        #pragma unroll
        for (int s = 0; s < 2; s++) {
            const uint32_t sOff = (uint32_t)(s * 32);
            uint32_t a1[2][4], a2[2][4];
            #pragma unroll
            for (int i = 0; i < 2; i++) {
                uint32_t ao = aOff + (uint32_t)(i * 16 * ROWB) + sOff;
                LDSM_X4(a1[i][0], a1[i][1], a1[i][2], a1[i][3], sb + SQ1A + ao);
                LDSM_X4(a2[i][0], a2[i][1], a2[i][2], a2[i][3], sb + SQ2A + ao);
            }
            uint32_t b1f[2][4], b2f[2][4];
            #pragma unroll
            for (int j2 = 0; j2 < 2; j2++) {
                uint32_t bo = bOff + (uint32_t)(j2 * 16 * ROWB) + sOff;
                LDSM_X4(b1f[j2][0], b1f[j2][1], b1f[j2][2], b1f[j2][3], sb + SQ1B + bo);
                LDSM_X4(b2f[j2][0], b2f[j2][1], b2f[j2][2], b2f[j2][3], sb + SQ2B + bo);
            }
            #pragma unroll
            for (int j = 0; j < 4; j++) {
                int j2 = j >> 1, jo = (j & 1) * 2;
                uint32_t b10 = b1f[j2][jo], b11 = b1f[j2][jo + 1];
                uint32_t b20 = b2f[j2][jo], b21 = b2f[j2][jo + 1];
                #pragma unroll
                for (int i = 0; i < 2; i++) {
                    mma_s8(accM[i][j], a1[i], b10, b11);   // q1*q1 (weight 16384)
                    mma_s8(accC[i][j], a1[i], b20, b21);   // q1*q2 (weight 128)
                    mma_s8(accC[i][j], a2[i], b10, b11);   // q2*q1 (weight 128)
                }
            }
        }
    }

    // ---- epilogue ----
    const int g = lane >> 2;
    #pragma unroll
    for (int i = 0; i < 2; i++) {
        int row0 = brow + wm * 32 + i * 16 + g;
        float sA0 = fsA[row0], sA1 = fsA[row0 + 8];
        #pragma unroll
        for (int j = 0; j < 4; j++) {
            int col = bcol + wn * 32 + j * 8 + (lane & 3) * 2;
            float sB0 = (col < N) ? fsB[col] : 0.0f;
            float sB1 = (col + 1 < N) ? fsB[col + 1] : 0.0f;
            #pragma unroll
            for (int half = 0; half < 2; half++) {
                int row = row0 + half * 8;
                float sA = half ? sA1 : sA0;
                float v0 = (16384.0f * (float)accM[i][j][half * 2 + 0]
                            + 128.0f * (float)accC[i][j][half * 2 + 0]) * sA * sB0;
                float v1 = (16384.0f * (float)accM[i][j][half * 2 + 1]
                            + 128.0f * (float)accC[i][j][half * 2 + 1]) * sA * sB1;
                if (mode == 1) {
                    v0 += bias[col]; v1 += bias[col + 1];
                    if (col < D_INNER) {
                        g_x[(size_t)row * D_INNER + col]     = v0;
                        g_x[(size_t)row * D_INNER + col + 1] = v1;
                    } else {
                        g_zs[(size_t)row * D_INNER + col - D_INNER]     = silu_f(v0);
                        g_zs[(size_t)row * D_INNER + col - D_INNER + 1] = silu_f(v1);
                    }
                } else if (mode == 0) {
                    if (col < N) {
                        size_t o = ((size_t)blockIdx.z * NTOK + row) * NPROJ + col;
                        g_Ppart[o]     = v0;
                        g_Ppart[o + 1] = v1;
                    }
                } else if (mode == 2) {
                    g_dt[(size_t)row * D_INNER + col]     = softplus_f(v0 + bias[col]);
                    g_dt[(size_t)row * D_INNER + col + 1] = softplus_f(v1 + bias[col + 1]);
                } else {
                    outp[(size_t)row * D_MODEL + col]     = v0 + bias[col];
                    outp[(size_t)row * D_MODEL + col + 1] = v1 + bias[col + 1];
                }
            }
        }
    }
}

// ---------------- reduce split-K partials of P -> Pf fp32 + BC ----------------
__global__ void reduce_P_kernel() {
    int i = blockIdx.x * 256 + threadIdx.x;
    if (i >= NTOK * NPROJ) return;
    int tok = i / NPROJ, col = i - tok * NPROJ;
    float s = g_Ppart[i] + g_Ppart[NTOK * NPROJ + i] +
              g_Ppart[2 * NTOK * NPROJ + i] + g_Ppart[3 * NTOK * NPROJ + i];
    if (col < DT_RANK) g_Pf[tok * DT_RANK + col] = s;
    else               g_BC[tok * (2 * D_STATE) + (col - DT_RANK)] = s;
}

// ---------------- causal depthwise conv (width 4) + silu ----------------
#define CONV_CHUNK 64
__global__ void conv_silu_kernel(const float* __restrict__ conv_w,
                                 const float* __restrict__ conv_b) {
    const int d  = blockIdx.x * 128 + threadIdx.x;
    const int l0 = blockIdx.y * CONV_CHUNK;
    const int b  = blockIdx.z;
    const float w0 = conv_w[d * 4 + 0], w1 = conv_w[d * 4 + 1];
    const float w2 = conv_w[d * 4 + 2], w3 = conv_w[d * 4 + 3];
    const float cb = conv_b[d];

    const int tok0 = b * SEQ + l0;
    float h0 = (l0 >= 3) ? g_x[(size_t)(tok0 - 3) * D_INNER + d] : 0.0f;
    float h1 = (l0 >= 2) ? g_x[(size_t)(tok0 - 2) * D_INNER + d] : 0.0f;
    float h2 = (l0 >= 1) ? g_x[(size_t)(tok0 - 1) * D_INNER + d] : 0.0f;

    #pragma unroll 4
    for (int l = l0; l < l0 + CONV_CHUNK; l++) {
        const size_t tok = (size_t)(b * SEQ + l);
        float cur = g_x[tok * D_INNER + d];
        float v = fmaf(w0, h0, fmaf(w1, h1, fmaf(w2, h2, fmaf(w3, cur, cb))));
        g_xc[tok * D_INNER + d] = silu_f(v);
        h0 = h1; h1 = h2; h2 = cur;
    }
}

// ---------------- selective scan (16 lanes per channel) ----------------
__global__ __launch_bounds__(256) void scan_kernel(const float* __restrict__ A_log,
                                                   const float* __restrict__ D_param) {
    const int gt = blockIdx.x * 256 + threadIdx.x;
    const int n  = gt & 15;
    const int ch = gt >> 4;
    const int b  = ch >> 12;
    const int d  = ch & (D_INNER - 1);

    const float a  = -__expf(A_log[d * D_STATE + n]);
    const float Dp = D_param[d];
    const bool writer = (n == 0);
    float h = 0.0f;

    const int tokbase = b * SEQ;
    #pragma unroll 4
    for (int t = 0; t < SEQ; t++) {
        const size_t tok = (size_t)(tokbase + t);
        const float dtv = g_dt[tok * D_INNER + d];
        const float xv  = g_xc[tok * D_INNER + d];
        const float Bv  = g_BC[tok * (2 * D_STATE) + n];
        const float Cv  = g_BC[tok * (2 * D_STATE) + D_STATE + n];

        const float dA = __expf(dtv * a);
        h = fmaf(h, dA, (xv * dtv) * Bv);

        float s = h * Cv;
        s += __shfl_xor_sync(0xffffffffu, s, 8);
        s += __shfl_xor_sync(0xffffffffu, s, 4);
        s += __shfl_xor_sync(0xffffffffu, s, 2);
        s += __shfl_xor_sync(0xffffffffu, s, 1);

        if (writer) {
            g_yf[tok * D_INNER + d] = (s + Dp * xv) * g_zs[tok * D_INNER + d];
        }
    }
}

// ---------------- launch ----------------
extern "C" void kernel_launch(void* const* d_in, const int* in_sizes, int n_in,
                              void* d_out, int out_size)
{
    const float* u      = (const float*)d_in[0];
    const float* w_in   = (const float*)d_in[1];
    const float* b_in   = (const float*)d_in[2];
    const float* w_out  = (const float*)d_in[3];
    const float* b_out  = (const float*)d_in[4];
    const float* w_dt   = (const float*)d_in[5];
    const float* b_dt   = (const float*)d_in[6];
    const float* w_xdt  = (const float*)d_in[7];
    const float* w_xb   = (const float*)d_in[8];
    const float* w_xc   = (const float*)d_in[9];
    const float* conv_w = (const float*)d_in[10];
    const float* conv_b = (const float*)d_in[11];
    const float* A_log  = (const float*)d_in[12];
    const float* D_par  = (const float*)d_in[13];
    float* out = (float*)d_out;

    cudaFuncSetAttribute(gemm_s8, cudaFuncAttributeMaxDynamicSharedMemorySize, GSMEM);

    int8_t *uq1, *uq2, *winq1, *winq2, *woutq1, *woutq2, *wdtq1, *wdtq2;
    int8_t *wcatq1, *wcatq2, *xcq1, *xcq2, *Pq1, *Pq2, *yq1, *yq2;
    float *ufs, *winfs, *woutfs, *wdtfs, *wcatfs, *xcfs, *Pfs, *yfs;
    float *wcatf, *xcf, *Pf, *yf;
    cudaGetSymbolAddress((void**)&uq1, g_uq1);     cudaGetSymbolAddress((void**)&uq2, g_uq2);
    cudaGetSymbolAddress((void**)&ufs, g_ufs);
    cudaGetSymbolAddress((void**)&winq1, g_winq1); cudaGetSymbolAddress((void**)&winq2, g_winq2);
    cudaGetSymbolAddress((void**)&winfs, g_winfs);
    cudaGetSymbolAddress((void**)&woutq1, g_woutq1); cudaGetSymbolAddress((void**)&woutq2, g_woutq2);
    cudaGetSymbolAddress((void**)&woutfs, g_woutfs);
    cudaGetSymbolAddress((void**)&wdtq1, g_wdtq1); cudaGetSymbolAddress((void**)&wdtq2, g_wdtq2);
    cudaGetSymbolAddress((void**)&wdtfs, g_wdtfs);
    cudaGetSymbolAddress((void**)&wcatq1, g_wcatq1); cudaGetSymbolAddress((void**)&wcatq2, g_wcatq2);
    cudaGetSymbolAddress((void**)&wcatfs, g_wcatfs);
    cudaGetSymbolAddress((void**)&xcq1, g_xcq1);   cudaGetSymbolAddress((void**)&xcq2, g_xcq2);
    cudaGetSymbolAddress((void**)&xcfs, g_xcfs);
    cudaGetSymbolAddress((void**)&Pq1, g_Pq1);     cudaGetSymbolAddress((void**)&Pq2, g_Pq2);
    cudaGetSymbolAddress((void**)&Pfs, g_Pfs);
    cudaGetSymbolAddress((void**)&yq1, g_yq1);     cudaGetSymbolAddress((void**)&yq2, g_yq2);
    cudaGetSymbolAddress((void**)&yfs, g_yfs);
    cudaGetSymbolAddress((void**)&wcatf, g_wcatf);
    cudaGetSymbolAddress((void**)&xcf, g_xc);
    cudaGetSymbolAddress((void**)&Pf, g_Pf);
    cudaGetSymbolAddress((void**)&yf, g_yf);

    // 0) quantize static inputs
    quant_rows<<<NTOK, 256>>>(u, uq1, uq2, ufs, D_MODEL);
    quant_rows<<<2 * D_INNER, 256>>>(w_in, winq1, winq2, winfs, D_MODEL);
    quant_rows<<<D_MODEL, 256>>>(w_out, woutq1, woutq2, woutfs, D_INNER);
    quant_rows<<<D_INNER, 256>>>(w_dt, wdtq1, wdtq2, wdtfs, DT_RANK);
    pack_wcat_kernel<<<(NPROJ * D_INNER + 255) / 256, 256>>>(w_xdt, w_xb, w_xc);
    quant_rows<<<NPROJ, 256>>>(wcatf, wcatq1, wcatq2, wcatfs, D_INNER);

    // 1) in_proj: [2048, 8192] = u @ w_in^T + b_in; x -> g_x, silu(z) -> g_zs
    {
        dim3 grid((2 * D_INNER) / GBN, NTOK / GBM, 1);
        gemm_s8<<<grid, 512, GSMEM>>>(2 * D_INNER, D_MODEL, D_MODEL,
                                      uq1, uq2, winq1, winq2, ufs, winfs, b_in, nullptr, 1);
    }

    // 2) depthwise conv + silu -> g_xc; quantize rows (K = D_INNER)
    {
        dim3 grid(D_INNER / 128, SEQ / CONV_CHUNK, B_SZ);
        conv_silu_kernel<<<grid, 128>>>(conv_w, conv_b);
        quant_rows<<<NTOK, 256>>>(xcf, xcq1, xcq2, xcfs, D_INNER);
    }

    // 3) x-proj (split-K=4): P[2048, 160] = xc @ wcat^T
    {
        dim3 grid((NPROJ + GBN - 1) / GBN, NTOK / GBM, 4);
        gemm_s8<<<grid, 512, GSMEM>>>(NPROJ, D_INNER, D_INNER / 4,
                                      xcq1, xcq2, wcatq1, wcatq2, xcfs, wcatfs, nullptr, nullptr, 0);
        reduce_P_kernel<<<(NTOK * NPROJ + 255) / 256, 256>>>();
        quant_rows<<<NTOK, 256>>>(Pf, Pq1, Pq2, Pfs, DT_RANK);
    }

    // 4) dt[2048, 4096] = softplus(P_low @ w_dt^T + b_dt)
    {
        dim3 grid(D_INNER / GBN, NTOK / GBM, 1);
        gemm_s8<<<grid, 512, GSMEM>>>(D_INNER, DT_RANK, DT_RANK,
                                      Pq1, Pq2, wdtq1, wdtq2, Pfs, wdtfs, b_dt, nullptr, 2);
    }

    // 5) selective scan + gating -> y fp32; quantize rows (K = D_INNER)
    scan_kernel<<<(B_SZ * D_INNER * D_STATE) / 256, 256>>>(A_log, D_par);
    quant_rows<<<NTOK, 256>>>(yf, yq1, yq2, yfs, D_INNER);

    // 6) out_proj: [2048, 2048] = y @ w_out^T + b_out
    {
        dim3 grid(D_MODEL / GBN, NTOK / GBM, 1);
        gemm_s8<<<grid, 512, GSMEM>>>(D_MODEL, D_INNER, D_INNER,
                                      yq1, yq2, woutq1, woutq2, yfs, woutfs, b_out, out, 3);
    }
}

// round 14
// speedup vs baseline: 2.4008x; 2.4008x over previous
#include <cuda_runtime.h>
#include <cuda_bf16.h>
#include <math.h>
#include <stdint.h>

// ---------------- problem constants ----------------
#define D_MODEL 2048
#define D_STATE 16
#define D_CONV  4
#define D_INNER 4096
#define DT_RANK 128
#define B_SZ    2
#define SEQ     1024
#define NTOK    (B_SZ * SEQ)             // 2048 tokens (= GEMM M)
#define NPROJ   (DT_RANK + 2 * D_STATE)  // 160

// ---------------- static device scratch ----------------
__device__ __nv_bfloat16 g_u_h [NTOK * D_MODEL];
__device__ __nv_bfloat16 g_u_l [NTOK * D_MODEL];
__device__ __nv_bfloat16 g_win_h[2 * D_INNER * D_MODEL];
__device__ __nv_bfloat16 g_win_l[2 * D_INNER * D_MODEL];
__device__ __nv_bfloat16 g_wout_h[D_MODEL * D_INNER];
__device__ __nv_bfloat16 g_wout_l[D_MODEL * D_INNER];
__device__ __nv_bfloat16 g_wdt_h[D_INNER * DT_RANK];
__device__ __nv_bfloat16 g_wdt_l[D_INNER * DT_RANK];
__device__ __nv_bfloat16 g_wcat_h[NPROJ * D_INNER];
__device__ __nv_bfloat16 g_wcat_l[NPROJ * D_INNER];

__device__ float g_x [NTOK * D_INNER];      // in_proj x half (pre-conv)
__device__ float g_zs[NTOK * D_INNER];      // silu(z)
__device__ float g_xc[NTOK * D_INNER];      // conv+silu (fp32, for scan)
__device__ __nv_bfloat16 g_xc_h[NTOK * D_INNER];
__device__ __nv_bfloat16 g_xc_l[NTOK * D_INNER];
__device__ float g_Ppart[4 * NTOK * NPROJ]; // split-K partials
__device__ __nv_bfloat16 g_P_h[NTOK * DT_RANK];
__device__ __nv_bfloat16 g_P_l[NTOK * DT_RANK];
__device__ float g_BC[NTOK * 2 * D_STATE];  // [tok][B(16)|C(16)]
__device__ float g_dt[NTOK * D_INNER];
__device__ __nv_bfloat16 g_y_h[NTOK * D_INNER];
__device__ __nv_bfloat16 g_y_l[NTOK * D_INNER];

// ---------------- helpers ----------------
__device__ __forceinline__ uint32_t smem_u32(const void* p) {
    uint32_t a;
    asm("{ .reg .u64 t; cvta.to.shared.u64 t, %1; cvt.u32.u64 %0, t; }" : "=r"(a) : "l"(p));
    return a;
}
__device__ __forceinline__ float silu_f(float v) { return v * (1.0f / (1.0f + __expf(-v))); }
__device__ __forceinline__ float softplus_f(float v) {
    return fmaxf(v, 0.0f) + log1pf(__expf(-fabsf(v)));
}
__device__ __forceinline__ void split2(float v, __nv_bfloat16* h, __nv_bfloat16* l) {
    __nv_bfloat16 hh = __float2bfloat16(v);
    *h = hh;
    *l = __float2bfloat16(v - __bfloat162float(hh));
}

__device__ __forceinline__ void cpa16(uint32_t dst, const void* src, int srcsz) {
    asm volatile("cp.async.cg.shared.global [%0], [%1], 16, %2;"
                 :: "r"(dst), "l"(src), "r"(srcsz) : "memory");
}
__device__ __forceinline__ void cp_commit() {
    asm volatile("cp.async.commit_group;" ::: "memory");
}
__device__ __forceinline__ void mma_bf16(float* d, const uint32_t* a, uint32_t b0, uint32_t b1) {
    asm volatile(
        "mma.sync.aligned.m16n8k16.row.col.f32.bf16.bf16.f32 "
        "{%0,%1,%2,%3}, {%4,%5,%6,%7}, {%8,%9}, {%0,%1,%2,%3};"
        : "+f"(d[0]), "+f"(d[1]), "+f"(d[2]), "+f"(d[3])
        : "r"(a[0]), "r"(a[1]), "r"(a[2]), "r"(a[3]), "r"(b0), "r"(b1));
}
#define LDSM_X4(r0, r1, r2, r3, addr) \
    asm volatile("ldmatrix.sync.aligned.m8n8.x4.shared.b16 {%0,%1,%2,%3}, [%4];" \
                 : "=r"(r0), "=r"(r1), "=r"(r2), "=r"(r3) : "r"(addr))

// ---------------- fp32 -> bf16 hi/lo converters (float4-vectorized) ----------------
__global__ void split_kernel(const float* __restrict__ src,
                             __nv_bfloat16* __restrict__ hi,
                             __nv_bfloat16* __restrict__ lo, int n4) {
    int i = blockIdx.x * 256 + threadIdx.x;
    if (i >= n4) return;
    float4 v = ((const float4*)src)[i];
    __nv_bfloat16 h[4], l[4];
    split2(v.x, h + 0, l + 0); split2(v.y, h + 1, l + 1);
    split2(v.z, h + 2, l + 2); split2(v.w, h + 3, l + 3);
    ((uint2*)hi)[i] = *(uint2*)h;
    ((uint2*)lo)[i] = *(uint2*)l;
}

__global__ void pack_wcat_kernel(const float* __restrict__ w_xdt,
                                 const float* __restrict__ w_xb,
                                 const float* __restrict__ w_xc) {
    int i = blockIdx.x * 256 + threadIdx.x;
    if (i >= NPROJ * D_INNER) return;
    int r = i / D_INNER, k = i - r * D_INNER;
    float v;
    if (r < DT_RANK)                v = w_xdt[r * D_INNER + k];
    else if (r < DT_RANK + D_STATE) v = w_xb[(r - DT_RANK) * D_INNER + k];
    else                            v = w_xc[(r - DT_RANK - D_STATE) * D_INNER + k];
    split2(v, g_wcat_h + i, g_wcat_l + i);
}

// ---------------- split-bf16 HMMA GEMM (mma.sync + ldmatrix, sm_80 ISA) ----------------
// C[2048, N] = A[2048, K] * W[N, K]^T via Ah*Bh + Ah*Bl + Al*Bh (fp32 accum).
// 128x128x32 CTA tile, 256 threads, 2x4 warps (64x32 warp tiles),
// cp.async double buffer with ONE __syncthreads per chunk (CUTLASS-style:
// the iter-c barrier already proves stage (c+1)&1 was consumed at iter c-1),
// 80B-padded smem rows (conflict-free LDSM), 2 CTAs/SM.
// mode: 1 in_proj   0 x-proj split-K partial   2 dt(softplus)   3 out
#define GBM 128
#define GBN 128
#define GBK 32
#define ROWB 80
#define TILE_B (128 * ROWB)          // 10240
#define ST_AH 0
#define ST_AL (TILE_B)
#define ST_BH (2 * TILE_B)
#define ST_BL (3 * TILE_B)
#define STAGE_B (4 * TILE_B)         // 40960
#define GSMEM (2 * STAGE_B)          // 81920

__global__ void __launch_bounds__(256, 2) gemm_bf16x3(
    int N, int K, int ksl,
    const __nv_bfloat16* __restrict__ Ah, const __nv_bfloat16* __restrict__ Al,
    const __nv_bfloat16* __restrict__ Bh, const __nv_bfloat16* __restrict__ Bl,
    const float* __restrict__ bias, float* __restrict__ outp, int mode)
{
    extern __shared__ char sm[];
    const uint32_t smb = smem_u32(sm);
    const int tid  = threadIdx.x;
    const int lane = tid & 31;
    const int wid  = tid >> 5;
    const int wm   = wid >> 2;           // 0..1
    const int wn   = wid & 3;            // 0..3

    const int brow  = blockIdx.y * GBM;
    const int bcol  = blockIdx.x * GBN;
    const int kbase = blockIdx.z * ksl;
    const int nchunks = ksl / GBK;

    // cp.async mapping: thread covers rows {tid>>2, 64+(tid>>2)}, 16B col (tid&3)
    const int lr = tid >> 2;             // 0..63
    const int lc = tid & 3;              // 0..3

    float acc[4][4][4];
    #pragma unroll
    for (int i = 0; i < 4; i++)
        #pragma unroll
        for (int j = 0; j < 4; j++)
            #pragma unroll
            for (int q = 0; q < 4; q++) acc[i][j][q] = 0.0f;

    auto load_stage = [&](int stage, int k0) {
        uint32_t sb = smb + stage * STAGE_B;
        #pragma unroll
        for (int h = 0; h < 2; h++) {
            int r = lr + h * 64;
            uint32_t soff = (uint32_t)(r * ROWB + lc * 16);
            size_t ga = (size_t)(brow + r) * K + k0 + lc * 8;
            cpa16(sb + ST_AH + soff, Ah + ga, 16);
            cpa16(sb + ST_AL + soff, Al + ga, 16);
            int gr = bcol + r;
            int sz = (gr < N) ? 16 : 0;
            int grc = (gr < N) ? gr : (N - 1);
            size_t gb = (size_t)grc * K + k0 + lc * 8;
            cpa16(sb + ST_BH + soff, Bh + gb, sz);
            cpa16(sb + ST_BL + soff, Bl + gb, sz);
        }
        cp_commit();
    };

    load_stage(0, kbase);

    // ldmatrix per-lane address components (layout validated: rel_err bit-match)
    const uint32_t aLaneOff = (uint32_t)((wm * 64 + (lane & 15)) * ROWB + (lane >> 4) * 16);
    const uint32_t bLaneOff = (uint32_t)((wn * 32 + ((lane >> 4) & 1) * 8 + (lane & 7)) * ROWB
                                         + ((lane >> 3) & 1) * 16);

    for (int c = 0; c < nchunks; c++) {
        asm volatile("cp.async.wait_group 0;" ::: "memory");
        __syncthreads();
        if (c + 1 < nchunks) load_stage((c + 1) & 1, kbase + (c + 1) * GBK);

        const uint32_t sb = smb + (c & 1) * STAGE_B;
        const uint32_t aH = sb + ST_AH + aLaneOff;
        const uint32_t aL = sb + ST_AL + aLaneOff;
        const uint32_t bH = sb + ST_BH + bLaneOff;
        const uint32_t bL = sb + ST_BL + bLaneOff;

        #pragma unroll
        for (int s = 0; s < 2; s++) {
            uint32_t ah[4][4], al[4][4];
            #pragma unroll
            for (int i = 0; i < 4; i++) {
                uint32_t ao = (uint32_t)(i * 16 * ROWB + s * 32);
                LDSM_X4(ah[i][0], ah[i][1], ah[i][2], ah[i][3], aH + ao);
                LDSM_X4(al[i][0], al[i][1], al[i][2], al[i][3], aL + ao);
            }
            #pragma unroll
            for (int j2 = 0; j2 < 2; j2++) {
                uint32_t bh[4], bl[4];
                uint32_t bo = (uint32_t)(j2 * 16 * ROWB + s * 32);
                LDSM_X4(bh[0], bh[1], bh[2], bh[3], bH + bo);
                LDSM_X4(bl[0], bl[1], bl[2], bl[3], bL + bo);
                #pragma unroll
                for (int jj = 0; jj < 2; jj++) {
                    int j = j2 * 2 + jj;
                    uint32_t b0h = bh[jj * 2], b1h = bh[jj * 2 + 1];
                    uint32_t b0l = bl[jj * 2], b1l = bl[jj * 2 + 1];
                    // product-major: same-acc MMAs are 4 apart (no tight RAW chain);
                    // per-acc accumulation order unchanged (hh, hl, lh) -> bit-identical
                    #pragma unroll
                    for (int i = 0; i < 4; i++) mma_bf16(acc[i][j], ah[i], b0h, b1h);
                    #pragma unroll
                    for (int i = 0; i < 4; i++) mma_bf16(acc[i][j], ah[i], b0l, b1l);
                    #pragma unroll
                    for (int i = 0; i < 4; i++) mma_bf16(acc[i][j], al[i], b0h, b1h);
                }
            }
        }
    }

    // ---- epilogue ----
    const int g = lane >> 2;
    #pragma unroll
    for (int i = 0; i < 4; i++) {
        int row0 = brow + wm * 64 + i * 16 + g;
        #pragma unroll
        for (int j = 0; j < 4; j++) {
            int col = bcol + wn * 32 + j * 8 + (lane & 3) * 2;
            #pragma unroll
            for (int half = 0; half < 2; half++) {
                int row = row0 + half * 8;
                float v0 = acc[i][j][half * 2 + 0];
                float v1 = acc[i][j][half * 2 + 1];
                if (mode == 1) {
                    v0 += bias[col]; v1 += bias[col + 1];
                    if (col < D_INNER) {
                        g_x[(size_t)row * D_INNER + col]     = v0;
                        g_x[(size_t)row * D_INNER + col + 1] = v1;
                    } else {
                        g_zs[(size_t)row * D_INNER + col - D_INNER]     = silu_f(v0);
                        g_zs[(size_t)row * D_INNER + col - D_INNER + 1] = silu_f(v1);
                    }
                } else if (mode == 0) {
                    if (col < N) {
                        size_t o = ((size_t)blockIdx.z * NTOK + row) * NPROJ + col;
                        g_Ppart[o]     = v0;
                        g_Ppart[o + 1] = v1;
                    }
                } else if (mode == 2) {
                    g_dt[(size_t)row * D_INNER + col]     = softplus_f(v0 + bias[col]);
                    g_dt[(size_t)row * D_INNER + col + 1] = softplus_f(v1 + bias[col + 1]);
                } else {
                    outp[(size_t)row * D_MODEL + col]     = v0 + bias[col];
                    outp[(size_t)row * D_MODEL + col + 1] = v1 + bias[col + 1];
                }
            }
        }
    }
}

// ---------------- reduce split-K partials of P; emit P hi/lo and B/C ----------------
__global__ void reduce_P_kernel() {
    int i = blockIdx.x * 256 + threadIdx.x;
    if (i >= NTOK * NPROJ) return;
    int tok = i / NPROJ, col = i - tok * NPROJ;
    float s = g_Ppart[i] + g_Ppart[NTOK * NPROJ + i] +
              g_Ppart[2 * NTOK * NPROJ + i] + g_Ppart[3 * NTOK * NPROJ + i];
    if (col < DT_RANK) split2(s, g_P_h + tok * DT_RANK + col, g_P_l + tok * DT_RANK + col);
    else               g_BC[tok * (2 * D_STATE) + (col - DT_RANK)] = s;
}

// ---------------- causal depthwise conv (width 4) + silu ----------------
#define CONV_CHUNK 64
__global__ void conv_silu_kernel(const float* __restrict__ conv_w,
                                 const float* __restrict__ conv_b) {
    const int d  = blockIdx.x * 128 + threadIdx.x;
    const int l0 = blockIdx.y * CONV_CHUNK;
    const int b  = blockIdx.z;
    const float w0 = conv_w[d * 4 + 0], w1 = conv_w[d * 4 + 1];
    const float w2 = conv_w[d * 4 + 2], w3 = conv_w[d * 4 + 3];
    const float cb = conv_b[d];

    const int tok0 = b * SEQ + l0;
    float h0 = (l0 >= 3) ? g_x[(size_t)(tok0 - 3) * D_INNER + d] : 0.0f;
    float h1 = (l0 >= 2) ? g_x[(size_t)(tok0 - 2) * D_INNER + d] : 0.0f;
    float h2 = (l0 >= 1) ? g_x[(size_t)(tok0 - 1) * D_INNER + d] : 0.0f;

    #pragma unroll 4
    for (int l = l0; l < l0 + CONV_CHUNK; l++) {
        const size_t tok = (size_t)(b * SEQ + l);
        float cur = g_x[tok * D_INNER + d];
        float v = fmaf(w0, h0, fmaf(w1, h1, fmaf(w2, h2, fmaf(w3, cur, cb))));
        v = silu_f(v);
        g_xc[tok * D_INNER + d] = v;
        split2(v, g_xc_h + tok * D_INNER + d, g_xc_l + tok * D_INNER + d);
        h0 = h1; h1 = h2; h2 = cur;
    }
}

// ---------------- selective scan (16 lanes per channel) ----------------
__global__ __launch_bounds__(256) void scan_kernel(const float* __restrict__ A_log,
                                                   const float* __restrict__ D_param) {
    const int gt = blockIdx.x * 256 + threadIdx.x;
    const int n  = gt & 15;
    const int ch = gt >> 4;
    const int b  = ch >> 12;
    const int d  = ch & (D_INNER - 1);

    const float a  = -__expf(A_log[d * D_STATE + n]);
    const float Dp = D_param[d];
    const bool writer = (n == 0);
    float h = 0.0f;

    const int tokbase = b * SEQ;
    #pragma unroll 4
    for (int t = 0; t < SEQ; t++) {
        const size_t tok = (size_t)(tokbase + t);
        const float dtv = g_dt[tok * D_INNER + d];
        const float xv  = g_xc[tok * D_INNER + d];
        const float Bv  = g_BC[tok * (2 * D_STATE) + n];
        const float Cv  = g_BC[tok * (2 * D_STATE) + D_STATE + n];

        const float dA = __expf(dtv * a);
        h = fmaf(h, dA, (xv * dtv) * Bv);

        float s = h * Cv;
        s += __shfl_xor_sync(0xffffffffu, s, 8);
        s += __shfl_xor_sync(0xffffffffu, s, 4);
        s += __shfl_xor_sync(0xffffffffu, s, 2);
        s += __shfl_xor_sync(0xffffffffu, s, 1);

        if (writer) {
            float y = (s + Dp * xv) * g_zs[tok * D_INNER + d];
            split2(y, g_y_h + tok * D_INNER + d, g_y_l + tok * D_INNER + d);
        }
    }
}

// ---------------- launch ----------------
extern "C" void kernel_launch(void* const* d_in, const int* in_sizes, int n_in,
                              void* d_out, int out_size)
{
    const float* u      = (const float*)d_in[0];
    const float* w_in   = (const float*)d_in[1];
    const float* b_in   = (const float*)d_in[2];
    const float* w_out  = (const float*)d_in[3];
    const float* b_out  = (const float*)d_in[4];
    const float* w_dt   = (const float*)d_in[5];
    const float* b_dt   = (const float*)d_in[6];
    const float* w_xdt  = (const float*)d_in[7];
    const float* w_xb   = (const float*)d_in[8];
    const float* w_xc   = (const float*)d_in[9];
    const float* conv_w = (const float*)d_in[10];
    const float* conv_b = (const float*)d_in[11];
    const float* A_log  = (const float*)d_in[12];
    const float* D_par  = (const float*)d_in[13];
    float* out = (float*)d_out;

    cudaFuncSetAttribute(gemm_bf16x3, cudaFuncAttributeMaxDynamicSharedMemorySize, GSMEM);

    __nv_bfloat16 *p_uh, *p_ul, *p_winh, *p_winl, *p_wouth, *p_woutl, *p_wdth, *p_wdtl;
    __nv_bfloat16 *p_wcath, *p_wcatl, *p_xch, *p_xcl, *p_Ph, *p_Pl, *p_yh, *p_yl;
    cudaGetSymbolAddress((void**)&p_uh,    g_u_h);   cudaGetSymbolAddress((void**)&p_ul,    g_u_l);
    cudaGetSymbolAddress((void**)&p_winh,  g_win_h); cudaGetSymbolAddress((void**)&p_winl,  g_win_l);
    cudaGetSymbolAddress((void**)&p_wouth, g_wout_h);cudaGetSymbolAddress((void**)&p_woutl, g_wout_l);
    cudaGetSymbolAddress((void**)&p_wdth,  g_wdt_h); cudaGetSymbolAddress((void**)&p_wdtl,  g_wdt_l);
    cudaGetSymbolAddress((void**)&p_wcath, g_wcat_h);cudaGetSymbolAddress((void**)&p_wcatl, g_wcat_l);
    cudaGetSymbolAddress((void**)&p_xch,   g_xc_h);  cudaGetSymbolAddress((void**)&p_xcl,   g_xc_l);
    cudaGetSymbolAddress((void**)&p_Ph,    g_P_h);   cudaGetSymbolAddress((void**)&p_Pl,    g_P_l);
    cudaGetSymbolAddress((void**)&p_yh,    g_y_h);   cudaGetSymbolAddress((void**)&p_yl,    g_y_l);

    // Launch order chosen so the in_proj GEMM is app-launch #4:
    // with the harness's +2 offset, ncu's "-s 5 -c 1" captures gemm_bf16x3.
    // 1) split u   2) split w_in   3) pack wcat   4) in_proj GEMM
    split_kernel<<<(NTOK * D_MODEL / 4 + 255) / 256, 256>>>(u, p_uh, p_ul, NTOK * D_MODEL / 4);
    split_kernel<<<(2 * D_INNER * D_MODEL / 4 + 255) / 256, 256>>>(w_in, p_winh, p_winl, 2 * D_INNER * D_MODEL / 4);
    pack_wcat_kernel<<<(NPROJ * D_INNER + 255) / 256, 256>>>(w_xdt, w_xb, w_xc);

    // in_proj: [2048, 8192] = u @ w_in^T + b_in; x -> g_x, silu(z) -> g_zs
    {
        dim3 grid((2 * D_INNER) / GBN, NTOK / GBM, 1);
        gemm_bf16x3<<<grid, 256, GSMEM>>>(2 * D_INNER, D_MODEL, D_MODEL,
                                          p_uh, p_ul, p_winh, p_winl, b_in, nullptr, 1);
    }

    // remaining weight splits (needed only by later GEMMs)
    split_kernel<<<(D_MODEL * D_INNER / 4 + 255) / 256, 256>>>(w_out, p_wouth, p_woutl, D_MODEL * D_INNER / 4);
    split_kernel<<<(D_INNER * DT_RANK / 4 + 255) / 256, 256>>>(w_dt, p_wdth, p_wdtl, D_INNER * DT_RANK / 4);

    // depthwise conv + silu -> g_xc (+ hi/lo)
    {
        dim3 grid(D_INNER / 128, SEQ / CONV_CHUNK, B_SZ);
        conv_silu_kernel<<<grid, 128>>>(conv_w, conv_b);
    }

    // x-proj (split-K=4): P[2048, 160] = xc @ wcat^T
    {
        dim3 grid((NPROJ + GBN - 1) / GBN, NTOK / GBM, 4);
        gemm_bf16x3<<<grid, 256, GSMEM>>>(NPROJ, D_INNER, D_INNER / 4,
                                          p_xch, p_xcl, p_wcath, p_wcatl, nullptr, nullptr, 0);
        reduce_P_kernel<<<(NTOK * NPROJ + 255) / 256, 256>>>();
    }

    // dt[2048, 4096] = softplus(P_low @ w_dt^T + b_dt)
    {
        dim3 grid(D_INNER / GBN, NTOK / GBM, 1);
        gemm_bf16x3<<<grid, 256, GSMEM>>>(D_INNER, DT_RANK, DT_RANK,
                                          p_Ph, p_Pl, p_wdth, p_wdtl, b_dt, nullptr, 2);
    }

    // selective scan + gating -> y hi/lo
    scan_kernel<<<(B_SZ * D_INNER * D_STATE) / 256, 256>>>(A_log, D_par);

    // out_proj: [2048, 2048] = y @ w_out^T + b_out
    {
        dim3 grid(D_MODEL / GBN, NTOK / GBM, 1);
        gemm_bf16x3<<<grid, 256, GSMEM>>>(D_MODEL, D_INNER, D_INNER,
                                          p_yh, p_yl, p_wouth, p_woutl, b_out, out, 3);
    }
}

// round 15
// speedup vs baseline: 3.3097x; 1.3786x over previous
#include <cuda_runtime.h>
#include <cuda_bf16.h>
#include <math.h>
#include <stdint.h>

// ---------------- problem constants ----------------
#define D_MODEL 2048
#define D_STATE 16
#define D_CONV  4
#define D_INNER 4096
#define DT_RANK 128
#define B_SZ    2
#define SEQ     1024
#define NTOK    (B_SZ * SEQ)             // 2048 tokens (= GEMM M)
#define NPROJ   (DT_RANK + 2 * D_STATE)  // 160

// ---------------- static device scratch ----------------
__device__ __nv_bfloat16 g_u_h [NTOK * D_MODEL];
__device__ __nv_bfloat16 g_u_l [NTOK * D_MODEL];
__device__ __nv_bfloat16 g_win_h[2 * D_INNER * D_MODEL];
__device__ __nv_bfloat16 g_win_l[2 * D_INNER * D_MODEL];
__device__ __nv_bfloat16 g_wout_h[D_MODEL * D_INNER];
__device__ __nv_bfloat16 g_wout_l[D_MODEL * D_INNER];
__device__ __nv_bfloat16 g_wdt_h[D_INNER * DT_RANK];
__device__ __nv_bfloat16 g_wdt_l[D_INNER * DT_RANK];
__device__ __nv_bfloat16 g_wcat_h[NPROJ * D_INNER];
__device__ __nv_bfloat16 g_wcat_l[NPROJ * D_INNER];

__device__ float g_x [NTOK * D_INNER];      // in_proj x half (pre-conv)
__device__ float g_zs[NTOK * D_INNER];      // silu(z)
__device__ __nv_bfloat16 g_xc_h[NTOK * D_INNER];
__device__ __nv_bfloat16 g_xc_l[NTOK * D_INNER];
__device__ uint32_t g_xc_pk[NTOK * D_INNER];   // packed (h | l<<16) for scan
__device__ float g_Ppart[4 * NTOK * NPROJ]; // split-K partials
__device__ __nv_bfloat16 g_P_h[NTOK * DT_RANK];
__device__ __nv_bfloat16 g_P_l[NTOK * DT_RANK];
__device__ float g_BC[NTOK * 2 * D_STATE];  // [tok][B(16)|C(16)]
__device__ float g_dt[NTOK * D_INNER];
__device__ __nv_bfloat16 g_y_h[NTOK * D_INNER];
__device__ __nv_bfloat16 g_y_l[NTOK * D_INNER];

// ---------------- helpers ----------------
__device__ __forceinline__ uint32_t smem_u32(const void* p) {
    uint32_t a;
    asm("{ .reg .u64 t; cvta.to.shared.u64 t, %1; cvt.u32.u64 %0, t; }" : "=r"(a) : "l"(p));
    return a;
}
__device__ __forceinline__ float silu_f(float v) { return v * (1.0f / (1.0f + __expf(-v))); }
__device__ __forceinline__ float softplus_f(float v) {
    return fmaxf(v, 0.0f) + log1pf(__expf(-fabsf(v)));
}
__device__ __forceinline__ void split2(float v, __nv_bfloat16* h, __nv_bfloat16* l) {
    __nv_bfloat16 hh = __float2bfloat16(v);
    *h = hh;
    *l = __float2bfloat16(v - __bfloat162float(hh));
}

__device__ __forceinline__ void cpa16(uint32_t dst, const void* src, int srcsz) {
    asm volatile("cp.async.cg.shared.global [%0], [%1], 16, %2;"
                 :: "r"(dst), "l"(src), "r"(srcsz) : "memory");
}
__device__ __forceinline__ void cp_commit() {
    asm volatile("cp.async.commit_group;" ::: "memory");
}
__device__ __forceinline__ void mma_bf16(float* d, const uint32_t* a, uint32_t b0, uint32_t b1) {
    asm volatile(
        "mma.sync.aligned.m16n8k16.row.col.f32.bf16.bf16.f32 "
        "{%0,%1,%2,%3}, {%4,%5,%6,%7}, {%8,%9}, {%0,%1,%2,%3};"
        : "+f"(d[0]), "+f"(d[1]), "+f"(d[2]), "+f"(d[3])
        : "r"(a[0]), "r"(a[1]), "r"(a[2]), "r"(a[3]), "r"(b0), "r"(b1));
}
#define LDSM_X4(r0, r1, r2, r3, addr) \
    asm volatile("ldmatrix.sync.aligned.m8n8.x4.shared.b16 {%0,%1,%2,%3}, [%4];" \
                 : "=r"(r0), "=r"(r1), "=r"(r2), "=r"(r3) : "r"(addr))

// ---------------- fp32 -> bf16 hi/lo converter, MLP=4 (4 independent float4) --------
// grid = n4/1024 exactly (all sizes divisible); each thread: 4 float4 at i + k*stride.
__global__ void split_kernel(const float* __restrict__ src,
                             __nv_bfloat16* __restrict__ hi,
                             __nv_bfloat16* __restrict__ lo, int n4) {
    const int stride = gridDim.x * 256;
    const int i = blockIdx.x * 256 + threadIdx.x;
    const float4* s4 = (const float4*)src;
    float4 v0 = s4[i];
    float4 v1 = s4[i + stride];
    float4 v2 = s4[i + 2 * stride];
    float4 v3 = s4[i + 3 * stride];
    float4 vv[4] = { v0, v1, v2, v3 };
    #pragma unroll
    for (int k = 0; k < 4; k++) {
        __nv_bfloat16 h[4], l[4];
        split2(vv[k].x, h + 0, l + 0); split2(vv[k].y, h + 1, l + 1);
        split2(vv[k].z, h + 2, l + 2); split2(vv[k].w, h + 3, l + 3);
        ((uint2*)hi)[i + k * stride] = *(uint2*)h;
        ((uint2*)lo)[i + k * stride] = *(uint2*)l;
    }
}

// pack + split x-proj weights, float4-wide
__global__ void pack_wcat_kernel(const float* __restrict__ w_xdt,
                                 const float* __restrict__ w_xb,
                                 const float* __restrict__ w_xc) {
    int i = blockIdx.x * 256 + threadIdx.x;        // float4 group index
    if (i >= NPROJ * D_INNER / 4) return;
    int r = i / (D_INNER / 4), kg = i - r * (D_INNER / 4);
    const float* srcrow;
    if (r < DT_RANK)                srcrow = w_xdt + (size_t)r * D_INNER;
    else if (r < DT_RANK + D_STATE) srcrow = w_xb + (size_t)(r - DT_RANK) * D_INNER;
    else                            srcrow = w_xc + (size_t)(r - DT_RANK - D_STATE) * D_INNER;
    float4 v = ((const float4*)srcrow)[kg];
    __nv_bfloat16 h[4], l[4];
    split2(v.x, h + 0, l + 0); split2(v.y, h + 1, l + 1);
    split2(v.z, h + 2, l + 2); split2(v.w, h + 3, l + 3);
    ((uint2*)g_wcat_h)[i] = *(uint2*)h;
    ((uint2*)g_wcat_l)[i] = *(uint2*)l;
}

// ---------------- split-bf16 HMMA GEMM (mma.sync + ldmatrix, sm_80 ISA) ----------------
// C[2048, N] = A[2048, K] * W[N, K]^T via Ah*Bh + Ah*Bl + Al*Bh (fp32 accum).
// 128x128x32 CTA tile, 256 threads, 2x4 warps, double buffer, one sync/chunk,
// 80B-padded rows (conflict-free LDSM), 2 CTAs/SM. Near legacy-HMMA ceiling.
// mode: 1 in_proj   0 x-proj split-K partial   2 dt(softplus)   3 out
#define GBM 128
#define GBN 128
#define GBK 32
#define ROWB 80
#define TILE_B (128 * ROWB)          // 10240
#define ST_AH 0
#define ST_AL (TILE_B)
#define ST_BH (2 * TILE_B)
#define ST_BL (3 * TILE_B)
#define STAGE_B (4 * TILE_B)         // 40960
#define GSMEM (2 * STAGE_B)          // 81920

__global__ void __launch_bounds__(256, 2) gemm_bf16x3(
    int N, int K, int ksl,
    const __nv_bfloat16* __restrict__ Ah, const __nv_bfloat16* __restrict__ Al,
    const __nv_bfloat16* __restrict__ Bh, const __nv_bfloat16* __restrict__ Bl,
    const float* __restrict__ bias, float* __restrict__ outp, int mode)
{
    extern __shared__ char sm[];
    const uint32_t smb = smem_u32(sm);
    const int tid  = threadIdx.x;
    const int lane = tid & 31;
    const int wid  = tid >> 5;
    const int wm   = wid >> 2;           // 0..1
    const int wn   = wid & 3;            // 0..3

    const int brow  = blockIdx.y * GBM;
    const int bcol  = blockIdx.x * GBN;
    const int kbase = blockIdx.z * ksl;
    const int nchunks = ksl / GBK;

    const int lr = tid >> 2;             // 0..63
    const int lc = tid & 3;              // 0..3

    float acc[4][4][4];
    #pragma unroll
    for (int i = 0; i < 4; i++)
        #pragma unroll
        for (int j = 0; j < 4; j++)
            #pragma unroll
            for (int q = 0; q < 4; q++) acc[i][j][q] = 0.0f;

    auto load_stage = [&](int stage, int k0) {
        uint32_t sb = smb + stage * STAGE_B;
        #pragma unroll
        for (int h = 0; h < 2; h++) {
            int r = lr + h * 64;
            uint32_t soff = (uint32_t)(r * ROWB + lc * 16);
            size_t ga = (size_t)(brow + r) * K + k0 + lc * 8;
            cpa16(sb + ST_AH + soff, Ah + ga, 16);
            cpa16(sb + ST_AL + soff, Al + ga, 16);
            int gr = bcol + r;
            int sz = (gr < N) ? 16 : 0;
            int grc = (gr < N) ? gr : (N - 1);
            size_t gb = (size_t)grc * K + k0 + lc * 8;
            cpa16(sb + ST_BH + soff, Bh + gb, sz);
            cpa16(sb + ST_BL + soff, Bl + gb, sz);
        }
        cp_commit();
    };

    load_stage(0, kbase);

    const uint32_t aLaneOff = (uint32_t)((wm * 64 + (lane & 15)) * ROWB + (lane >> 4) * 16);
    const uint32_t bLaneOff = (uint32_t)((wn * 32 + ((lane >> 4) & 1) * 8 + (lane & 7)) * ROWB
                                         + ((lane >> 3) & 1) * 16);

    for (int c = 0; c < nchunks; c++) {
        asm volatile("cp.async.wait_group 0;" ::: "memory");
        __syncthreads();
        if (c + 1 < nchunks) load_stage((c + 1) & 1, kbase + (c + 1) * GBK);

        const uint32_t sb = smb + (c & 1) * STAGE_B;
        const uint32_t aH = sb + ST_AH + aLaneOff;
        const uint32_t aL = sb + ST_AL + aLaneOff;
        const uint32_t bH = sb + ST_BH + bLaneOff;
        const uint32_t bL = sb + ST_BL + bLaneOff;

        #pragma unroll
        for (int s = 0; s < 2; s++) {
            uint32_t ah[4][4], al[4][4];
            #pragma unroll
            for (int i = 0; i < 4; i++) {
                uint32_t ao = (uint32_t)(i * 16 * ROWB + s * 32);
                LDSM_X4(ah[i][0], ah[i][1], ah[i][2], ah[i][3], aH + ao);
                LDSM_X4(al[i][0], al[i][1], al[i][2], al[i][3], aL + ao);
            }
            #pragma unroll
            for (int j2 = 0; j2 < 2; j2++) {
                uint32_t bh[4], bl[4];
                uint32_t bo = (uint32_t)(j2 * 16 * ROWB + s * 32);
                LDSM_X4(bh[0], bh[1], bh[2], bh[3], bH + bo);
                LDSM_X4(bl[0], bl[1], bl[2], bl[3], bL + bo);
                #pragma unroll
                for (int jj = 0; jj < 2; jj++) {
                    int j = j2 * 2 + jj;
                    uint32_t b0h = bh[jj * 2], b1h = bh[jj * 2 + 1];
                    uint32_t b0l = bl[jj * 2], b1l = bl[jj * 2 + 1];
                    #pragma unroll
                    for (int i = 0; i < 4; i++) mma_bf16(acc[i][j], ah[i], b0h, b1h);
                    #pragma unroll
                    for (int i = 0; i < 4; i++) mma_bf16(acc[i][j], ah[i], b0l, b1l);
                    #pragma unroll
                    for (int i = 0; i < 4; i++) mma_bf16(acc[i][j], al[i], b0h, b1h);
                }
            }
        }
    }

    // ---- epilogue ----
    const int g = lane >> 2;
    #pragma unroll
    for (int i = 0; i < 4; i++) {
        int row0 = brow + wm * 64 + i * 16 + g;
        #pragma unroll
        for (int j = 0; j < 4; j++) {
            int col = bcol + wn * 32 + j * 8 + (lane & 3) * 2;
            #pragma unroll
            for (int half = 0; half < 2; half++) {
                int row = row0 + half * 8;
                float v0 = acc[i][j][half * 2 + 0];
                float v1 = acc[i][j][half * 2 + 1];
                if (mode == 1) {
                    v0 += bias[col]; v1 += bias[col + 1];
                    if (col < D_INNER) {
                        g_x[(size_t)row * D_INNER + col]     = v0;
                        g_x[(size_t)row * D_INNER + col + 1] = v1;
                    } else {
                        g_zs[(size_t)row * D_INNER + col - D_INNER]     = silu_f(v0);
                        g_zs[(size_t)row * D_INNER + col - D_INNER + 1] = silu_f(v1);
                    }
                } else if (mode == 0) {
                    if (col < N) {
                        size_t o = ((size_t)blockIdx.z * NTOK + row) * NPROJ + col;
                        g_Ppart[o]     = v0;
                        g_Ppart[o + 1] = v1;
                    }
                } else if (mode == 2) {
                    g_dt[(size_t)row * D_INNER + col]     = softplus_f(v0 + bias[col]);
                    g_dt[(size_t)row * D_INNER + col + 1] = softplus_f(v1 + bias[col + 1]);
                } else {
                    outp[(size_t)row * D_MODEL + col]     = v0 + bias[col];
                    outp[(size_t)row * D_MODEL + col + 1] = v1 + bias[col + 1];
                }
            }
        }
    }
}

// ---------------- reduce split-K partials of P; emit P hi/lo and B/C ----------------
__global__ void reduce_P_kernel() {
    int i = blockIdx.x * 256 + threadIdx.x;
    if (i >= NTOK * NPROJ) return;
    int tok = i / NPROJ, col = i - tok * NPROJ;
    float s = g_Ppart[i] + g_Ppart[NTOK * NPROJ + i] +
              g_Ppart[2 * NTOK * NPROJ + i] + g_Ppart[3 * NTOK * NPROJ + i];
    if (col < DT_RANK) split2(s, g_P_h + tok * DT_RANK + col, g_P_l + tok * DT_RANK + col);
    else               g_BC[tok * (2 * D_STATE) + (col - DT_RANK)] = s;
}

// ---------------- causal depthwise conv (width 4) + silu, float4 over channels -------
#define CONV_CHUNK 32
__global__ void conv_silu_kernel(const float* __restrict__ conv_w,
                                 const float* __restrict__ conv_b) {
    const int dg = blockIdx.x * 128 + threadIdx.x;   // 0..1023 (D_INNER/4 groups)
    const int d  = dg << 2;
    const int l0 = blockIdx.y * CONV_CHUNK;
    const int b  = blockIdx.z;

    float4 wt0 = ((const float4*)conv_w)[dg * 4 + 0];
    float4 wt1 = ((const float4*)conv_w)[dg * 4 + 1];
    float4 wt2 = ((const float4*)conv_w)[dg * 4 + 2];
    float4 wt3 = ((const float4*)conv_w)[dg * 4 + 3];
    float4 cb  = ((const float4*)conv_b)[dg];

    const int tok0 = b * SEQ + l0;
    const float4 zero = make_float4(0.f, 0.f, 0.f, 0.f);
    float4 h0 = (l0 >= 3) ? *(const float4*)(g_x + (size_t)(tok0 - 3) * D_INNER + d) : zero;
    float4 h1 = (l0 >= 2) ? *(const float4*)(g_x + (size_t)(tok0 - 2) * D_INNER + d) : zero;
    float4 h2 = (l0 >= 1) ? *(const float4*)(g_x + (size_t)(tok0 - 1) * D_INNER + d) : zero;

    #pragma unroll 4
    for (int l = l0; l < l0 + CONV_CHUNK; l++) {
        const size_t tok = (size_t)(b * SEQ + l);
        float4 cur = *(const float4*)(g_x + tok * D_INNER + d);
        float v0 = fmaf(wt0.x, h0.x, fmaf(wt0.y, h1.x, fmaf(wt0.z, h2.x, fmaf(wt0.w, cur.x, cb.x))));
        float v1 = fmaf(wt1.x, h0.y, fmaf(wt1.y, h1.y, fmaf(wt1.z, h2.y, fmaf(wt1.w, cur.y, cb.y))));
        float v2 = fmaf(wt2.x, h0.z, fmaf(wt2.y, h1.z, fmaf(wt2.z, h2.z, fmaf(wt2.w, cur.z, cb.z))));
        float v3 = fmaf(wt3.x, h0.w, fmaf(wt3.y, h1.w, fmaf(wt3.z, h2.w, fmaf(wt3.w, cur.w, cb.w))));
        v0 = silu_f(v0); v1 = silu_f(v1); v2 = silu_f(v2); v3 = silu_f(v3);
        __nv_bfloat16 hh[4], ll[4];
        split2(v0, hh + 0, ll + 0); split2(v1, hh + 1, ll + 1);
        split2(v2, hh + 2, ll + 2); split2(v3, hh + 3, ll + 3);
        *(uint2*)(g_xc_h + tok * D_INNER + d) = *(uint2*)hh;
        *(uint2*)(g_xc_l + tok * D_INNER + d) = *(uint2*)ll;
        uint32_t pk[4];
        #pragma unroll
        for (int q = 0; q < 4; q++)
            pk[q] = (uint32_t)__bfloat16_as_ushort(hh[q]) | ((uint32_t)__bfloat16_as_ushort(ll[q]) << 16);
        *(uint4*)(g_xc_pk + tok * D_INNER + d) = *(uint4*)pk;
        h0 = h1; h1 = h2; h2 = cur;
    }
}

// ---------------- selective scan (16 lanes per channel, prefetched) ----------------
__global__ __launch_bounds__(256) void scan_kernel(const float* __restrict__ A_log,
                                                   const float* __restrict__ D_param) {
    const int gt = blockIdx.x * 256 + threadIdx.x;
    const int n  = gt & 15;
    const int ch = gt >> 4;
    const int b  = ch >> 12;
    const int d  = ch & (D_INNER - 1);

    const float a  = -__expf(A_log[d * D_STATE + n]);
    const float Dp = D_param[d];
    const bool writer = (n == 0);
    float h = 0.0f;

    const int tokbase = b * SEQ;
    size_t tk = (size_t)tokbase;
    float    dt_n = g_dt[tk * D_INNER + d];
    uint32_t xp_n = g_xc_pk[tk * D_INNER + d];
    float    B_n  = g_BC[tk * (2 * D_STATE) + n];
    float    C_n  = g_BC[tk * (2 * D_STATE) + D_STATE + n];

    for (int t = 0; t < SEQ; t++) {
        const float dtv = dt_n;
        const uint32_t xp = xp_n;
        const float Bv = B_n, Cv = C_n;
        if (t < SEQ - 1) {
            size_t tk2 = (size_t)(tokbase + t + 1);
            dt_n = g_dt[tk2 * D_INNER + d];
            xp_n = g_xc_pk[tk2 * D_INNER + d];
            B_n  = g_BC[tk2 * (2 * D_STATE) + n];
            C_n  = g_BC[tk2 * (2 * D_STATE) + D_STATE + n];
        }
        const float xv = __bfloat162float(__ushort_as_bfloat16((unsigned short)(xp & 0xffff)))
                       + __bfloat162float(__ushort_as_bfloat16((unsigned short)(xp >> 16)));

        const float dA = __expf(dtv * a);
        h = fmaf(h, dA, (xv * dtv) * Bv);

        float s = h * Cv;
        s += __shfl_xor_sync(0xffffffffu, s, 8);
        s += __shfl_xor_sync(0xffffffffu, s, 4);
        s += __shfl_xor_sync(0xffffffffu, s, 2);
        s += __shfl_xor_sync(0xffffffffu, s, 1);

        if (writer) {
            const size_t tok = (size_t)(tokbase + t);
            float y = (s + Dp * xv) * g_zs[tok * D_INNER + d];
            split2(y, g_y_h + tok * D_INNER + d, g_y_l + tok * D_INNER + d);
        }
    }
}

// ---------------- launch ----------------
extern "C" void kernel_launch(void* const* d_in, const int* in_sizes, int n_in,
                              void* d_out, int out_size)
{
    const float* u      = (const float*)d_in[0];
    const float* w_in   = (const float*)d_in[1];
    const float* b_in   = (const float*)d_in[2];
    const float* w_out  = (const float*)d_in[3];
    const float* b_out  = (const float*)d_in[4];
    const float* w_dt   = (const float*)d_in[5];
    const float* b_dt   = (const float*)d_in[6];
    const float* w_xdt  = (const float*)d_in[7];
    const float* w_xb   = (const float*)d_in[8];
    const float* w_xc   = (const float*)d_in[9];
    const float* conv_w = (const float*)d_in[10];
    const float* conv_b = (const float*)d_in[11];
    const float* A_log  = (const float*)d_in[12];
    const float* D_par  = (const float*)d_in[13];
    float* out = (float*)d_out;

    cudaFuncSetAttribute(gemm_bf16x3, cudaFuncAttributeMaxDynamicSharedMemorySize, GSMEM);

    __nv_bfloat16 *p_uh, *p_ul, *p_winh, *p_winl, *p_wouth, *p_woutl, *p_wdth, *p_wdtl;
    __nv_bfloat16 *p_wcath, *p_wcatl, *p_xch, *p_xcl, *p_Ph, *p_Pl, *p_yh, *p_yl;
    cudaGetSymbolAddress((void**)&p_uh,    g_u_h);   cudaGetSymbolAddress((void**)&p_ul,    g_u_l);
    cudaGetSymbolAddress((void**)&p_winh,  g_win_h); cudaGetSymbolAddress((void**)&p_winl,  g_win_l);
    cudaGetSymbolAddress((void**)&p_wouth, g_wout_h);cudaGetSymbolAddress((void**)&p_woutl, g_wout_l);
    cudaGetSymbolAddress((void**)&p_wdth,  g_wdt_h); cudaGetSymbolAddress((void**)&p_wdtl,  g_wdt_l);
    cudaGetSymbolAddress((void**)&p_wcath, g_wcat_h);cudaGetSymbolAddress((void**)&p_wcatl, g_wcat_l);
    cudaGetSymbolAddress((void**)&p_xch,   g_xc_h);  cudaGetSymbolAddress((void**)&p_xcl,   g_xc_l);
    cudaGetSymbolAddress((void**)&p_Ph,    g_P_h);   cudaGetSymbolAddress((void**)&p_Pl,    g_P_l);
    cudaGetSymbolAddress((void**)&p_yh,    g_y_h);   cudaGetSymbolAddress((void**)&p_yl,    g_y_l);

    // Launch order keeps in_proj GEMM at app-launch #4 (ncu -s 5 -c 1 captures it).
    // 1) split u   2) split w_in   3) pack wcat   4) in_proj GEMM
    split_kernel<<<(NTOK * D_MODEL / 4) / 1024, 256>>>(u, p_uh, p_ul, NTOK * D_MODEL / 4);
    split_kernel<<<(2 * D_INNER * D_MODEL / 4) / 1024, 256>>>(w_in, p_winh, p_winl, 2 * D_INNER * D_MODEL / 4);
    pack_wcat_kernel<<<(NPROJ * D_INNER / 4 + 255) / 256, 256>>>(w_xdt, w_xb, w_xc);

    // in_proj: [2048, 8192] = u @ w_in^T + b_in; x -> g_x, silu(z) -> g_zs
    {
        dim3 grid((2 * D_INNER) / GBN, NTOK / GBM, 1);
        gemm_bf16x3<<<grid, 256, GSMEM>>>(2 * D_INNER, D_MODEL, D_MODEL,
                                          p_uh, p_ul, p_winh, p_winl, b_in, nullptr, 1);
    }

    // remaining weight splits (needed only by later GEMMs)
    split_kernel<<<(D_MODEL * D_INNER / 4) / 1024, 256>>>(w_out, p_wouth, p_woutl, D_MODEL * D_INNER / 4);
    split_kernel<<<(D_INNER * DT_RANK / 4) / 1024, 256>>>(w_dt, p_wdth, p_wdtl, D_INNER * DT_RANK / 4);

    // depthwise conv + silu -> xc_h/xc_l + packed
    {
        dim3 grid((D_INNER / 4) / 128, SEQ / CONV_CHUNK, B_SZ);
        conv_silu_kernel<<<grid, 128>>>(conv_w, conv_b);
    }

    // x-proj (split-K=4): P[2048, 160] = xc @ wcat^T
    {
        dim3 grid((NPROJ + GBN - 1) / GBN, NTOK / GBM, 4);
        gemm_bf16x3<<<grid, 256, GSMEM>>>(NPROJ, D_INNER, D_INNER / 4,
                                          p_xch, p_xcl, p_wcath, p_wcatl, nullptr, nullptr, 0);
        reduce_P_kernel<<<(NTOK * NPROJ + 255) / 256, 256>>>();
    }

    // dt[2048, 4096] = softplus(P_low @ w_dt^T + b_dt)
    {
        dim3 grid(D_INNER / GBN, NTOK / GBM, 1);
        gemm_bf16x3<<<grid, 256, GSMEM>>>(D_INNER, DT_RANK, DT_RANK,
                                          p_Ph, p_Pl, p_wdth, p_wdtl, b_dt, nullptr, 2);
    }

    // selective scan + gating -> y hi/lo
    scan_kernel<<<(B_SZ * D_INNER * D_STATE) / 256, 256>>>(A_log, D_par);

    // out_proj: [2048, 2048] = y @ w_out^T + b_out
    {
        dim3 grid(D_MODEL / GBN, NTOK / GBM, 1);
        gemm_bf16x3<<<grid, 256, GSMEM>>>(D_MODEL, D_INNER, D_INNER,
                                          p_yh, p_yl, p_wouth, p_woutl, b_out, out, 3);
    }
}